// round 1
// baseline (speedup 1.0000x reference)
#include <cuda_runtime.h>
#include <cuda_bf16.h>
#include <math.h>

// Problem constants
#define BB 8
#define LL 2048
#define DD 1330
#define H1C 32
#define H2C 16
// T = 2 (hardcoded throughout)

#define NEGINF (-1e30f)

// Scratch (device globals; no allocation allowed)
__device__ float g_h1[BB * LL * H1C];   // [B*L, 32]
__device__ float g_em[BB * LL * 2];     // [B*L, 2]
__device__ float g_llh[BB];

// ---------------------------------------------------------------------------
// Kernel A: h1 = x @ w1 + b1     (M=16384, K=1330, N=32)
// 64-row tiles, 128 threads, 4x4 register microtiles.
// ---------------------------------------------------------------------------
__global__ __launch_bounds__(128) void gemm1_kernel(
    const float* __restrict__ x, const float* __restrict__ w1,
    const float* __restrict__ b1)
{
    __shared__ float xs[64][33];   // [row][k], padded to avoid bank conflicts
    __shared__ float ws[32][32];   // [k][c]

    const int tid = threadIdx.x;
    const int row0 = blockIdx.x * 64;
    const int rg = tid >> 3;          // 0..15
    const int cg = tid & 7;           // 0..7
    const int r0 = rg * 4, c0 = cg * 4;
    const int lwarp = tid >> 5;       // 0..3
    const int lane = tid & 31;

    float acc[4][4];
#pragma unroll
    for (int i = 0; i < 4; i++)
#pragma unroll
        for (int j = 0; j < 4; j++) acc[i][j] = 0.f;

    for (int k0 = 0; k0 < DD; k0 += 32) {
        // load w1 tile (1024 floats / 128 threads)
#pragma unroll
        for (int i = 0; i < 8; i++) {
            int idx = tid + i * 128;
            int kk = idx >> 5, c = idx & 31;
            int k = k0 + kk;
            ws[kk][c] = (k < DD) ? w1[k * H1C + c] : 0.f;
        }
        // load x tile: each warp loads rows lwarp, lwarp+4, ... (coalesced over k)
        {
            int k = k0 + lane;
            bool ok = (k < DD);
#pragma unroll
            for (int r = 0; r < 16; r++) {
                int rr = r * 4 + lwarp;
                xs[rr][lane] = ok ? x[(size_t)(row0 + rr) * DD + k] : 0.f;
            }
        }
        __syncthreads();
#pragma unroll
        for (int kk = 0; kk < 32; kk++) {
            float4 wv = *(const float4*)&ws[kk][c0];
            float x0 = xs[r0 + 0][kk];
            float x1 = xs[r0 + 1][kk];
            float x2 = xs[r0 + 2][kk];
            float x3 = xs[r0 + 3][kk];
            acc[0][0] += x0 * wv.x; acc[0][1] += x0 * wv.y; acc[0][2] += x0 * wv.z; acc[0][3] += x0 * wv.w;
            acc[1][0] += x1 * wv.x; acc[1][1] += x1 * wv.y; acc[1][2] += x1 * wv.z; acc[1][3] += x1 * wv.w;
            acc[2][0] += x2 * wv.x; acc[2][1] += x2 * wv.y; acc[2][2] += x2 * wv.z; acc[2][3] += x2 * wv.w;
            acc[3][0] += x3 * wv.x; acc[3][1] += x3 * wv.y; acc[3][2] += x3 * wv.z; acc[3][3] += x3 * wv.w;
        }
        __syncthreads();
    }

    float4 bv = *(const float4*)&b1[c0];
#pragma unroll
    for (int j = 0; j < 4; j++) {
        float4 o;
        o.x = acc[j][0] + bv.x;
        o.y = acc[j][1] + bv.y;
        o.z = acc[j][2] + bv.z;
        o.w = acc[j][3] + bv.w;
        *(float4*)&g_h1[(size_t)(row0 + r0 + j) * H1C + c0] = o;
    }
}

// ---------------------------------------------------------------------------
// Kernel B: conv1d(k=3, pad=1, 32->16) + bias + relu + gemm2 (16->2) + b2
// One thread per (b,l).
// ---------------------------------------------------------------------------
__global__ __launch_bounds__(256) void conv_gemm2_kernel(
    const float* __restrict__ conv_w, const float* __restrict__ conv_b,
    const float* __restrict__ w2, const float* __restrict__ b2)
{
    __shared__ float wst[96][16];   // [k*32+c1][c2]
    __shared__ float cb[16];
    __shared__ float w2s[16][2];
    __shared__ float b2s[2];

    const int tid = threadIdx.x;
    for (int i = tid; i < 96 * 16; i += 256) {
        int q = i >> 4, c2 = i & 15;
        int k = q >> 5, c1 = q & 31;
        wst[q][c2] = conv_w[c2 * 96 + c1 * 3 + k];   // conv_w [c2][c1][k]
    }
    if (tid < 16) cb[tid] = conv_b[tid];
    if (tid < 32) w2s[tid >> 1][tid & 1] = w2[tid];
    if (tid < 2) b2s[tid] = b2[tid];
    __syncthreads();

    const int idx = blockIdx.x * 256 + tid;   // 0..16383
    const int l = idx & (LL - 1);
    const float* base = g_h1 + (size_t)idx * H1C;

    float hreg[96];
    const bool hasL = (l > 0), hasR = (l < LL - 1);
#pragma unroll
    for (int c1 = 0; c1 < 32; c1 += 4) {
        float4 v = hasL ? *(const float4*)(base - 32 + c1) : make_float4(0, 0, 0, 0);
        hreg[c1] = v.x; hreg[c1 + 1] = v.y; hreg[c1 + 2] = v.z; hreg[c1 + 3] = v.w;
    }
#pragma unroll
    for (int c1 = 0; c1 < 32; c1 += 4) {
        float4 v = *(const float4*)(base + c1);
        hreg[32 + c1] = v.x; hreg[33 + c1] = v.y; hreg[34 + c1] = v.z; hreg[35 + c1] = v.w;
    }
#pragma unroll
    for (int c1 = 0; c1 < 32; c1 += 4) {
        float4 v = hasR ? *(const float4*)(base + 32 + c1) : make_float4(0, 0, 0, 0);
        hreg[64 + c1] = v.x; hreg[65 + c1] = v.y; hreg[66 + c1] = v.z; hreg[67 + c1] = v.w;
    }

    float4 acc[4];
#pragma unroll
    for (int m = 0; m < 4; m++) acc[m] = make_float4(0, 0, 0, 0);
#pragma unroll
    for (int q = 0; q < 96; q++) {
        float hv = hreg[q];
#pragma unroll
        for (int m = 0; m < 4; m++) {
            float4 w = *(const float4*)&wst[q][m * 4];
            acc[m].x += hv * w.x; acc[m].y += hv * w.y;
            acc[m].z += hv * w.z; acc[m].w += hv * w.w;
        }
    }
    float af[16];
#pragma unroll
    for (int m = 0; m < 4; m++) {
        af[m * 4 + 0] = acc[m].x; af[m * 4 + 1] = acc[m].y;
        af[m * 4 + 2] = acc[m].z; af[m * 4 + 3] = acc[m].w;
    }
    float e0 = b2s[0], e1 = b2s[1];
#pragma unroll
    for (int c2 = 0; c2 < 16; c2++) {
        float h = fmaxf(af[c2] + cb[c2], 0.f);
        e0 += h * w2s[c2][0];
        e1 += h * w2s[c2][1];
    }
    float2 eo = make_float2(e0, e1);
    *(float2*)&g_em[(size_t)idx * 2] = eo;
}

// ---------------------------------------------------------------------------
// Kernel C: CRF via associative scans.
// float4 matrix layout: {x=a00, y=a01, z=a10, w=a11}
// ---------------------------------------------------------------------------
__device__ __forceinline__ float lse2(float p, float q) {
    float mx = fmaxf(p, q), mn = fminf(p, q);
    return mx + log1pf(__expf(mn - mx));
}
__device__ __forceinline__ float4 lse_mm(float4 A, float4 B) {
    float4 C;
    C.x = lse2(A.x + B.x, A.y + B.z);
    C.y = lse2(A.x + B.y, A.y + B.w);
    C.z = lse2(A.z + B.x, A.w + B.z);
    C.w = lse2(A.z + B.y, A.w + B.w);
    return C;
}
__device__ __forceinline__ float4 max_mm(float4 A, float4 B) {
    float4 C;
    C.x = fmaxf(A.x + B.x, A.y + B.z);
    C.y = fmaxf(A.x + B.y, A.y + B.w);
    C.z = fmaxf(A.z + B.x, A.w + B.z);
    C.w = fmaxf(A.z + B.y, A.w + B.w);
    return C;
}
__device__ __forceinline__ unsigned comp2(unsigned a, unsigned b) {
    // (a o b)(x) = a(b(x)); maps {0,1}->{0,1} coded as bit0=f(0), bit1=f(1)
    unsigned r0 = (a >> (b & 1)) & 1;
    unsigned r1 = (a >> ((b >> 1) & 1)) & 1;
    return r0 | (r1 << 1);
}

__global__ __launch_bounds__(256) void crf_kernel(
    const int* __restrict__ tlen, const int* __restrict__ labels,
    const float* __restrict__ start_trans, const float* __restrict__ end_trans,
    const float* __restrict__ trans, float* __restrict__ out)
{
    __shared__ float4 sf[256];
    __shared__ float4 sv[256];
    __shared__ unsigned char scomp[256];
    __shared__ float sred[256];

    const int b = blockIdx.x, tid = threadIdx.x;
    const int len = tlen[b];
    const float t00 = trans[0], t01 = trans[1], t10 = trans[2], t11 = trans[3];
    const float* emb = g_em + (size_t)b * LL * 2;

    // ---- per-thread chunk products over steps t = tid*8+1 .. tid*8+8 ----
    float4 Pf = make_float4(0.f, NEGINF, NEGINF, 0.f);
    float4 Pv = Pf;
#pragma unroll
    for (int k = 1; k <= 8; k++) {
        int t = tid * 8 + k;
        if (t < len) {
            float m0 = emb[2 * t], m1 = emb[2 * t + 1];
            float4 M = make_float4(t00 + m0, t01 + m1, t10 + m0, t11 + m1);
            Pf = lse_mm(Pf, M);
            Pv = max_mm(Pv, M);
        }
    }
    sf[tid] = Pf; sv[tid] = Pv;
    __syncthreads();

    // ---- Hillis-Steele inclusive scans (left-to-right product) ----
    for (int off = 1; off < 256; off <<= 1) {
        float4 nf, nv;
        bool p = (tid >= off);
        if (p) { nf = lse_mm(sf[tid - off], sf[tid]); nv = max_mm(sv[tid - off], sv[tid]); }
        __syncthreads();
        if (p) { sf[tid] = nf; sv[tid] = nv; }
        __syncthreads();
    }

    const float a00 = start_trans[0] + emb[0];
    const float a01 = start_trans[1] + emb[1];
    const float e0 = end_trans[0], e1 = end_trans[1];

    // log-partition
    float4 PF = sf[255];
    float f0 = lse2(a00 + PF.x, a01 + PF.z);
    float f1 = lse2(a00 + PF.y, a01 + PF.w);
    float norm = lse2(f0 + e0, f1 + e1);

    // viterbi final
    float4 PV = sv[255];
    float v0 = fmaxf(a00 + PV.x, a01 + PV.z);
    float v1 = fmaxf(a00 + PV.y, a01 + PV.w);
    int last = (v1 + e1 > v0 + e0) ? 1 : 0;

    // ---- viterbi hist per chunk (needs exclusive max-plus prefix) ----
    float4 E = (tid == 0) ? make_float4(0.f, NEGINF, NEGINF, 0.f) : sv[tid - 1];
    float u0 = fmaxf(a00 + E.x, a01 + E.z);
    float u1 = fmaxf(a00 + E.y, a01 + E.w);
    unsigned g[8];
    unsigned cc = 2u;   // identity map
#pragma unroll
    for (int k = 1; k <= 8; k++) {
        int t = tid * 8 + k;
        unsigned gt;
        if (t < len) {
            float m0 = emb[2 * t], m1 = emb[2 * t + 1];
            float s00 = u0 + t00, s10 = u1 + t10;
            int i0 = (s10 > s00) ? 1 : 0;
            float n0 = fmaxf(s00, s10) + m0;
            float s01 = u0 + t01, s11 = u1 + t11;
            int i1 = (s11 > s01) ? 1 : 0;
            float n1 = fmaxf(s01, s11) + m1;
            gt = (unsigned)(i0 | (i1 << 1));
            u0 = n0; u1 = n1;
        } else {
            gt = 2u;   // identity
        }
        g[k - 1] = gt;
        cc = comp2(cc, gt);   // chunkcomp = g_{first} o ... o g_{last}
    }
    scomp[tid] = (unsigned char)cc;
    __syncthreads();

    // ---- suffix scan of compositions ----
    for (int off = 1; off < 256; off <<= 1) {
        unsigned nc = 0;
        bool p = (tid + off < 256);
        if (p) nc = comp2(scomp[tid], scomp[tid + off]);
        __syncthreads();
        if (p) scomp[tid] = (unsigned char)nc;
        __syncthreads();
    }
    unsigned suf_next = (tid == 255) ? 2u : (unsigned)scomp[tid + 1];
    unsigned xx = (suf_next >> last) & 1u;

    // ---- emit tags (positions tid*8 .. tid*8+7) ----
    float* tout = out + 1 + (size_t)b * LL;
#pragma unroll
    for (int k = 8; k >= 1; k--) {
        xx = (g[k - 1] >> xx) & 1u;
        int pos = tid * 8 + k - 1;
        tout[pos] = (pos < len) ? (float)xx : 0.f;
    }

    // ---- gold score ----
    const int* lab = labels + (size_t)b * LL;
    float sc = 0.f;
#pragma unroll
    for (int k = 1; k <= 8; k++) {
        int t = tid * 8 + k;
        if (t < len) {
            int lp = lab[t - 1], lc = lab[t];
            sc += trans[lp * 2 + lc] + emb[2 * t + lc];
        }
    }
    sred[tid] = sc;
    __syncthreads();
    for (int off = 128; off > 0; off >>= 1) {
        if (tid < off) sred[tid] += sred[tid + off];
        __syncthreads();
    }
    if (tid == 0) {
        int l0 = lab[0];
        float total = sred[0] + start_trans[l0] + emb[l0];
        int le = lab[len - 1];
        total += end_trans[le];
        g_llh[b] = total - norm;
    }
}

// ---------------------------------------------------------------------------
// Kernel D: neg_loss = -sum(llh)
// ---------------------------------------------------------------------------
__global__ void finalize_kernel(float* __restrict__ out) {
    float s = 0.f;
#pragma unroll
    for (int i = 0; i < BB; i++) s += g_llh[i];
    out[0] = -s;
}

extern "C" void kernel_launch(void* const* d_in, const int* in_sizes, int n_in,
                              void* d_out, int out_size)
{
    const float* x       = (const float*)d_in[0];
    const int*   tlen    = (const int*)d_in[1];
    const int*   labels  = (const int*)d_in[2];
    const float* w1      = (const float*)d_in[3];
    const float* b1      = (const float*)d_in[4];
    const float* conv_w  = (const float*)d_in[5];
    const float* conv_b  = (const float*)d_in[6];
    const float* w2      = (const float*)d_in[7];
    const float* b2      = (const float*)d_in[8];
    const float* st      = (const float*)d_in[9];
    const float* en      = (const float*)d_in[10];
    const float* tr      = (const float*)d_in[11];
    float* out = (float*)d_out;

    gemm1_kernel<<<256, 128>>>(x, w1, b1);
    conv_gemm2_kernel<<<64, 256>>>(conv_w, conv_b, w2, b2);
    crf_kernel<<<BB, 256>>>(tlen, labels, st, en, tr, out);
    finalize_kernel<<<1, 1>>>(out);
}

// round 2
// speedup vs baseline: 1.3332x; 1.3332x over previous
#include <cuda_runtime.h>
#include <cuda_bf16.h>
#include <math.h>

// Problem constants
#define BB 8
#define LL 2048
#define DD 1330
#define H1C 32
// T = 2 (hardcoded throughout)

#define NEGINF (-1e30f)

// Scratch (device globals; no allocation allowed)
__device__ float g_p0[BB * LL * H1C];   // split-K partial 0
__device__ float g_p1[BB * LL * H1C];   // split-K partial 1
__device__ float g_em[BB * LL * 2];     // [B*L, 2]
__device__ float g_llh[BB];
__device__ unsigned g_done;

// ---------------------------------------------------------------------------
// Kernel A: partial = x @ w1 over a K-slice, 3xTF32 tensor-core GEMM.
// M=16384, N=32, K=1330 split into 2 slices of 672 (21 tiles of BK=32).
// Block: 128 threads (4 warps), BM=128. Warp w covers rows 32w..32w+31, all 32 cols.
// ---------------------------------------------------------------------------
#define MMA_TF32(c, a0, a1, a2, a3, b0, b1)                                   \
    asm volatile(                                                             \
        "mma.sync.aligned.m16n8k8.row.col.f32.tf32.tf32.f32 "                 \
        "{%0,%1,%2,%3}, {%4,%5,%6,%7}, {%8,%9}, {%0,%1,%2,%3};"               \
        : "+f"(c[0]), "+f"(c[1]), "+f"(c[2]), "+f"(c[3])                      \
        : "r"(a0), "r"(a1), "r"(a2), "r"(a3), "r"(b0), "r"(b1))

__device__ __forceinline__ unsigned cvt_tf32(float v) {
    unsigned r;
    asm("cvt.rna.tf32.f32 %0, %1;" : "=r"(r) : "f"(v));
    return r;
}

__global__ __launch_bounds__(128) void gemm1_mma(
    const float* __restrict__ x, const float* __restrict__ w1)
{
    __shared__ float xhi[128][36];
    __shared__ float xlo[128][36];
    __shared__ float bhi[4][4][32][2];   // [kchunk][ngroup][lane][reg]
    __shared__ float blo[4][4][32][2];

    const int tid = threadIdx.x;
    const int warp = tid >> 5, lane = tid & 31;
    const int gr = lane >> 2, gc = lane & 3;
    const int row0 = blockIdx.x * 128;
    const int kbase = blockIdx.y * 672;
    const int NT = 21;

    const int jj = tid & 15;       // k-pair index (k = 2*jj, 2*jj+1)
    const int rld = tid >> 4;      // row base 0..7

    float acc[2][4][4];
#pragma unroll
    for (int h = 0; h < 2; h++)
#pragma unroll
        for (int n = 0; n < 4; n++)
#pragma unroll
            for (int r = 0; r < 4; r++) acc[h][n][r] = 0.f;

    float2 xv[16];
    float wv[8];

    // ---- prefetch tile 0 ----
    {
        int k0 = kbase;
        int kq = k0 + 2 * jj;
        bool ok = (kq < DD);
#pragma unroll
        for (int i = 0; i < 16; i++) {
            int r = row0 + rld + 8 * i;
            xv[i] = ok ? *(const float2*)(x + (size_t)r * DD + kq)
                       : make_float2(0.f, 0.f);
        }
#pragma unroll
        for (int i = 0; i < 8; i++) {
            int idx = i * 128 + tid;
            int kk = idx >> 5, c = idx & 31;
            int k = k0 + kk;
            wv[i] = (k < DD) ? w1[k * H1C + c] : 0.f;
        }
    }

    for (int t = 0; t < NT; t++) {
        __syncthreads();
        // ---- STS phase: split into hi/lo tf32 and store ----
#pragma unroll
        for (int i = 0; i < 16; i++) {
            unsigned h0 = cvt_tf32(xv[i].x);
            unsigned h1 = cvt_tf32(xv[i].y);
            float l0 = xv[i].x - __uint_as_float(h0);
            float l1 = xv[i].y - __uint_as_float(h1);
            unsigned q0 = cvt_tf32(l0);
            unsigned q1 = cvt_tf32(l1);
            int r = rld + 8 * i;
            *(float2*)&xhi[r][2 * jj] =
                make_float2(__uint_as_float(h0), __uint_as_float(h1));
            *(float2*)&xlo[r][2 * jj] =
                make_float2(__uint_as_float(q0), __uint_as_float(q1));
        }
#pragma unroll
        for (int i = 0; i < 8; i++) {
            int idx = i * 128 + tid;
            int kk = idx >> 5, c = idx & 31;
            unsigned h = cvt_tf32(wv[i]);
            float lo = wv[i] - __uint_as_float(h);
            unsigned q = cvt_tf32(lo);
            int chunk = kk >> 3;
            int reg = (kk >> 2) & 1;
            int lanep = (c & 7) * 4 + (kk & 3);
            int ng = c >> 3;
            bhi[chunk][ng][lanep][reg] = __uint_as_float(h);
            blo[chunk][ng][lanep][reg] = __uint_as_float(q);
        }
        __syncthreads();

        // ---- prefetch next tile ----
        if (t + 1 < NT) {
            int k0 = kbase + (t + 1) * 32;
            int kq = k0 + 2 * jj;
            bool ok = (kq < DD);
#pragma unroll
            for (int i = 0; i < 16; i++) {
                int r = row0 + rld + 8 * i;
                xv[i] = ok ? *(const float2*)(x + (size_t)r * DD + kq)
                           : make_float2(0.f, 0.f);
            }
#pragma unroll
            for (int i = 0; i < 8; i++) {
                int idx = i * 128 + tid;
                int kk = idx >> 5, c = idx & 31;
                int k = k0 + kk;
                wv[i] = (k < DD) ? w1[k * H1C + c] : 0.f;
            }
        }

        // ---- compute tile ----
#pragma unroll
        for (int ch = 0; ch < 4; ch++) {
            int kc = ch * 8;
            float2 bh[4], bl[4];
#pragma unroll
            for (int ng = 0; ng < 4; ng++) {
                bh[ng] = *(float2*)&bhi[ch][ng][lane][0];
                bl[ng] = *(float2*)&blo[ch][ng][lane][0];
            }
#pragma unroll
            for (int h = 0; h < 2; h++) {
                int rb = warp * 32 + h * 16;
                unsigned ah0 = __float_as_uint(xhi[rb + gr][kc + gc]);
                unsigned ah1 = __float_as_uint(xhi[rb + 8 + gr][kc + gc]);
                unsigned ah2 = __float_as_uint(xhi[rb + gr][kc + gc + 4]);
                unsigned ah3 = __float_as_uint(xhi[rb + 8 + gr][kc + gc + 4]);
                unsigned al0 = __float_as_uint(xlo[rb + gr][kc + gc]);
                unsigned al1 = __float_as_uint(xlo[rb + 8 + gr][kc + gc]);
                unsigned al2 = __float_as_uint(xlo[rb + gr][kc + gc + 4]);
                unsigned al3 = __float_as_uint(xlo[rb + 8 + gr][kc + gc + 4]);
#pragma unroll
                for (int ng = 0; ng < 4; ng++) {
                    unsigned bh0 = __float_as_uint(bh[ng].x);
                    unsigned bh1 = __float_as_uint(bh[ng].y);
                    unsigned bl0 = __float_as_uint(bl[ng].x);
                    unsigned bl1 = __float_as_uint(bl[ng].y);
                    MMA_TF32(acc[h][ng], ah0, ah1, ah2, ah3, bh0, bh1);
                    MMA_TF32(acc[h][ng], ah0, ah1, ah2, ah3, bl0, bl1);
                    MMA_TF32(acc[h][ng], al0, al1, al2, al3, bh0, bh1);
                }
            }
        }
    }

    // ---- epilogue: write partial ----
    float* gp = blockIdx.y ? g_p1 : g_p0;
#pragma unroll
    for (int h = 0; h < 2; h++) {
        int row = row0 + warp * 32 + h * 16 + gr;
#pragma unroll
        for (int ng = 0; ng < 4; ng++) {
            int col = ng * 8 + 2 * gc;
            *(float2*)&gp[(size_t)row * H1C + col] =
                make_float2(acc[h][ng][0], acc[h][ng][1]);
            *(float2*)&gp[(size_t)(row + 8) * H1C + col] =
                make_float2(acc[h][ng][2], acc[h][ng][3]);
        }
    }
}

// ---------------------------------------------------------------------------
// Kernel B: sum partials + bias, conv1d(k=3,pad=1,32->16)+relu, gemm2(16->2).
// 64 blocks x 256 threads; block covers 256 positions (aligned within batch).
// ---------------------------------------------------------------------------
__global__ __launch_bounds__(256) void conv_gemm2_kernel(
    const float* __restrict__ conv_w, const float* __restrict__ conv_b,
    const float* __restrict__ w2, const float* __restrict__ b2,
    const float* __restrict__ b1)
{
    __shared__ float hs[258][33];   // halo tile of h1
    __shared__ float wst[96][16];   // [k*32+c1][c2]
    __shared__ float cb[16];
    __shared__ float w2s[16][2];
    __shared__ float b2s[2];

    const int tid = threadIdx.x;
    if (blockIdx.x == 0 && tid == 0) g_done = 0;

    for (int i = tid; i < 96 * 16; i += 256) {
        int q = i >> 4, c2 = i & 15;
        int k = q >> 5, c1 = q & 31;
        wst[q][c2] = conv_w[c2 * 96 + c1 * 3 + k];   // conv_w [c2][c1][k]
    }
    if (tid < 16) cb[tid] = conv_b[tid];
    if (tid < 32) w2s[tid >> 1][tid & 1] = w2[tid];
    if (tid < 2) b2s[tid] = b2[tid];

    const int p0 = blockIdx.x * 256;
    const int lblk = p0 & (LL - 1);

    for (int idx = tid; idx < 258 * 32; idx += 256) {
        int row = idx >> 5, c = idx & 31;
        int l = lblk - 1 + row;
        float v = 0.f;
        if (l >= 0 && l < LL) {
            int g = p0 + row - 1;
            v = g_p0[(size_t)g * H1C + c] + g_p1[(size_t)g * H1C + c] + __ldg(&b1[c]);
        }
        hs[row][c] = v;
    }
    __syncthreads();

    // compute position p0 + tid; conv inputs are hs rows tid, tid+1, tid+2
    float4 acc[4];
#pragma unroll
    for (int m = 0; m < 4; m++) acc[m] = make_float4(0, 0, 0, 0);
#pragma unroll
    for (int kk = 0; kk < 3; kk++) {
#pragma unroll
        for (int c1 = 0; c1 < 32; c1++) {
            float hv = hs[tid + kk][c1];
            int q = kk * 32 + c1;
#pragma unroll
            for (int m = 0; m < 4; m++) {
                float4 w = *(const float4*)&wst[q][m * 4];
                acc[m].x += hv * w.x; acc[m].y += hv * w.y;
                acc[m].z += hv * w.z; acc[m].w += hv * w.w;
            }
        }
    }
    float af[16];
#pragma unroll
    for (int m = 0; m < 4; m++) {
        af[m * 4 + 0] = acc[m].x; af[m * 4 + 1] = acc[m].y;
        af[m * 4 + 2] = acc[m].z; af[m * 4 + 3] = acc[m].w;
    }
    float e0 = b2s[0], e1 = b2s[1];
#pragma unroll
    for (int c2 = 0; c2 < 16; c2++) {
        float h = fmaxf(af[c2] + cb[c2], 0.f);
        e0 += h * w2s[c2][0];
        e1 += h * w2s[c2][1];
    }
    *(float2*)&g_em[(size_t)(p0 + tid) * 2] = make_float2(e0, e1);
}

// ---------------------------------------------------------------------------
// Kernel C: CRF via associative scans (+ merged final reduction).
// float4 matrix layout: {x=a00, y=a01, z=a10, w=a11}
// ---------------------------------------------------------------------------
__device__ __forceinline__ float lse2(float p, float q) {
    float mx = fmaxf(p, q), mn = fminf(p, q);
    return mx + log1pf(__expf(mn - mx));
}
__device__ __forceinline__ float4 lse_mm(float4 A, float4 B) {
    float4 C;
    C.x = lse2(A.x + B.x, A.y + B.z);
    C.y = lse2(A.x + B.y, A.y + B.w);
    C.z = lse2(A.z + B.x, A.w + B.z);
    C.w = lse2(A.z + B.y, A.w + B.w);
    return C;
}
__device__ __forceinline__ float4 max_mm(float4 A, float4 B) {
    float4 C;
    C.x = fmaxf(A.x + B.x, A.y + B.z);
    C.y = fmaxf(A.x + B.y, A.y + B.w);
    C.z = fmaxf(A.z + B.x, A.w + B.z);
    C.w = fmaxf(A.z + B.y, A.w + B.w);
    return C;
}
__device__ __forceinline__ unsigned comp2(unsigned a, unsigned b) {
    unsigned r0 = (a >> (b & 1)) & 1;
    unsigned r1 = (a >> ((b >> 1) & 1)) & 1;
    return r0 | (r1 << 1);
}

__global__ __launch_bounds__(256) void crf_kernel(
    const int* __restrict__ tlen, const int* __restrict__ labels,
    const float* __restrict__ start_trans, const float* __restrict__ end_trans,
    const float* __restrict__ trans, float* __restrict__ out)
{
    __shared__ float4 sf[256];
    __shared__ float4 sv[256];
    __shared__ unsigned char scomp[256];
    __shared__ float sred[256];

    const int b = blockIdx.x, tid = threadIdx.x;
    const int len = tlen[b];
    const float t00 = trans[0], t01 = trans[1], t10 = trans[2], t11 = trans[3];
    const float* emb = g_em + (size_t)b * LL * 2;

    // ---- per-thread chunk products over steps t = tid*8+1 .. tid*8+8 ----
    float4 Pf = make_float4(0.f, NEGINF, NEGINF, 0.f);
    float4 Pv = Pf;
#pragma unroll
    for (int k = 1; k <= 8; k++) {
        int t = tid * 8 + k;
        if (t < len) {
            float m0 = emb[2 * t], m1 = emb[2 * t + 1];
            float4 M = make_float4(t00 + m0, t01 + m1, t10 + m0, t11 + m1);
            Pf = lse_mm(Pf, M);
            Pv = max_mm(Pv, M);
        }
    }
    sf[tid] = Pf; sv[tid] = Pv;
    __syncthreads();

    // ---- Hillis-Steele inclusive scans ----
    for (int off = 1; off < 256; off <<= 1) {
        float4 nf, nv;
        bool p = (tid >= off);
        if (p) { nf = lse_mm(sf[tid - off], sf[tid]); nv = max_mm(sv[tid - off], sv[tid]); }
        __syncthreads();
        if (p) { sf[tid] = nf; sv[tid] = nv; }
        __syncthreads();
    }

    const float a00 = start_trans[0] + emb[0];
    const float a01 = start_trans[1] + emb[1];
    const float e0 = end_trans[0], e1 = end_trans[1];

    float4 PF = sf[255];
    float f0 = lse2(a00 + PF.x, a01 + PF.z);
    float f1 = lse2(a00 + PF.y, a01 + PF.w);
    float norm = lse2(f0 + e0, f1 + e1);

    float4 PV = sv[255];
    float v0 = fmaxf(a00 + PV.x, a01 + PV.z);
    float v1 = fmaxf(a00 + PV.y, a01 + PV.w);
    int last = (v1 + e1 > v0 + e0) ? 1 : 0;

    // ---- viterbi hist per chunk (exclusive max-plus prefix) ----
    float4 E = (tid == 0) ? make_float4(0.f, NEGINF, NEGINF, 0.f) : sv[tid - 1];
    float u0 = fmaxf(a00 + E.x, a01 + E.z);
    float u1 = fmaxf(a00 + E.y, a01 + E.w);
    unsigned g[8];
    unsigned cc = 2u;   // identity map
#pragma unroll
    for (int k = 1; k <= 8; k++) {
        int t = tid * 8 + k;
        unsigned gt;
        if (t < len) {
            float m0 = emb[2 * t], m1 = emb[2 * t + 1];
            float s00 = u0 + t00, s10 = u1 + t10;
            int i0 = (s10 > s00) ? 1 : 0;
            float n0 = fmaxf(s00, s10) + m0;
            float s01 = u0 + t01, s11 = u1 + t11;
            int i1 = (s11 > s01) ? 1 : 0;
            float n1 = fmaxf(s01, s11) + m1;
            gt = (unsigned)(i0 | (i1 << 1));
            u0 = n0; u1 = n1;
        } else {
            gt = 2u;   // identity
        }
        g[k - 1] = gt;
        cc = comp2(cc, gt);
    }
    scomp[tid] = (unsigned char)cc;
    __syncthreads();

    // ---- suffix scan of compositions ----
    for (int off = 1; off < 256; off <<= 1) {
        unsigned nc = 0;
        bool p = (tid + off < 256);
        if (p) nc = comp2(scomp[tid], scomp[tid + off]);
        __syncthreads();
        if (p) scomp[tid] = (unsigned char)nc;
        __syncthreads();
    }
    unsigned suf_next = (tid == 255) ? 2u : (unsigned)scomp[tid + 1];
    unsigned xx = (suf_next >> last) & 1u;

    // ---- emit tags ----
    float* tout = out + 1 + (size_t)b * LL;
#pragma unroll
    for (int k = 8; k >= 1; k--) {
        xx = (g[k - 1] >> xx) & 1u;
        int pos = tid * 8 + k - 1;
        tout[pos] = (pos < len) ? (float)xx : 0.f;
    }

    // ---- gold score ----
    const int* lab = labels + (size_t)b * LL;
    float sc = 0.f;
#pragma unroll
    for (int k = 1; k <= 8; k++) {
        int t = tid * 8 + k;
        if (t < len) {
            int lp = lab[t - 1], lc = lab[t];
            sc += trans[lp * 2 + lc] + emb[2 * t + lc];
        }
    }
    sred[tid] = sc;
    __syncthreads();
    for (int off = 128; off > 0; off >>= 1) {
        if (tid < off) sred[tid] += sred[tid + off];
        __syncthreads();
    }
    if (tid == 0) {
        int l0 = lab[0];
        float total = sred[0] + start_trans[l0] + emb[l0];
        int le = lab[len - 1];
        total += end_trans[le];
        g_llh[b] = total - norm;
        __threadfence();
        unsigned old = atomicAdd(&g_done, 1);
        if (old == BB - 1) {
            __threadfence();
            float s = 0.f;
#pragma unroll
            for (int i = 0; i < BB; i++) s += ((volatile float*)g_llh)[i];
            out[0] = -s;
        }
    }
}

extern "C" void kernel_launch(void* const* d_in, const int* in_sizes, int n_in,
                              void* d_out, int out_size)
{
    const float* x       = (const float*)d_in[0];
    const int*   tlen    = (const int*)d_in[1];
    const int*   labels  = (const int*)d_in[2];
    const float* w1      = (const float*)d_in[3];
    const float* b1      = (const float*)d_in[4];
    const float* conv_w  = (const float*)d_in[5];
    const float* conv_b  = (const float*)d_in[6];
    const float* w2      = (const float*)d_in[7];
    const float* b2      = (const float*)d_in[8];
    const float* st      = (const float*)d_in[9];
    const float* en      = (const float*)d_in[10];
    const float* tr      = (const float*)d_in[11];
    float* out = (float*)d_out;

    gemm1_mma<<<dim3(128, 2), 128>>>(x, w1);
    conv_gemm2_kernel<<<64, 256>>>(conv_w, conv_b, w2, b2, b1);
    crf_kernel<<<BB, 256>>>(tlen, labels, st, en, tr, out);
}